// round 9
// baseline (speedup 1.0000x reference)
#include <cuda_runtime.h>
#include <cuda_bf16.h>
#include <cuda_fp16.h>
#include <cstdint>

// Problem constants (match reference_code)
#define NN 50000      // nodes
#define EE 800000     // edges
#define IN_F 128
#define DD 64
#define HH 4
#define HD 256        // H*D
#define NEG_SLOPE 0.2f

// ---------------------------------------------------------------------------
// Scratch (static __device__ arrays — no allocation allowed)
// ---------------------------------------------------------------------------
__device__ __half   g_feat_h[(size_t)NN * HD]; // projected features [N,256] fp16
__device__ float    g_h[(size_t)NN * HD];      // layer io buffer (fp32)
__device__ float    g_el[(size_t)NN * HH];
__device__ float    g_er[(size_t)NN * HH];
__device__ int      g_rowptr[NN + 1];
__device__ int      g_cur[NN];
__device__ int      g_csr[EE];                 // src per CSR slot (sorted by dst)
// W in mma-fragment order, all 4 layers: uint4 = {bh0,bh1,bl0,bl1}
// layer0 (K=128): 8192 uint4; layers1-3 (K=64): 4096 uint4 each
__device__ uint4    g_Wf[8192 + 3 * 4096];

// ---------------------------------------------------------------------------
// CSR build: zero -> histogram(dst) -> scan -> scatter
// ---------------------------------------------------------------------------
__global__ void zero_cur_k() {
    int i = blockIdx.x * blockDim.x + threadIdx.x;
    if (i < NN) g_cur[i] = 0;
}

__global__ void hist_k(const int* __restrict__ dst) {
    int e = blockIdx.x * blockDim.x + threadIdx.x;
    if (e < EE) atomicAdd(&g_cur[dst[e]], 1);
}

// single-block exclusive scan over g_cur -> g_rowptr; 4 elems/thread/iter.
// Also re-zeros g_cur. NN % 4 == 0.
__global__ void scan_k() {
    __shared__ int ws[32];
    __shared__ int s_carry;
    int t = threadIdx.x, lane = t & 31, wid = t >> 5;
    if (t == 0) s_carry = 0;
    __syncthreads();
    for (int base = 0; base < NN; base += 4096) {
        int i0 = base + t * 4;
        int4 v = make_int4(0, 0, 0, 0);
        if (i0 < NN) {
            v = *(const int4*)&g_cur[i0];
            *(int4*)&g_cur[i0] = make_int4(0, 0, 0, 0);
        }
        int tsum = v.x + v.y + v.z + v.w;
        int x = tsum;
        #pragma unroll
        for (int o = 1; o < 32; o <<= 1) {
            int y = __shfl_up_sync(0xffffffffu, x, o);
            if (lane >= o) x += y;
        }
        if (lane == 31) ws[wid] = x;
        __syncthreads();
        if (wid == 0) {
            int y = ws[lane];
            #pragma unroll
            for (int o = 1; o < 32; o <<= 1) {
                int z = __shfl_up_sync(0xffffffffu, y, o);
                if (lane >= o) y += z;
            }
            ws[lane] = y;
        }
        __syncthreads();
        int excl = x - tsum + (wid ? ws[wid - 1] : 0) + s_carry;
        if (i0 < NN) {
            g_rowptr[i0]     = excl;
            g_rowptr[i0 + 1] = excl + v.x;
            g_rowptr[i0 + 2] = excl + v.x + v.y;
            g_rowptr[i0 + 3] = excl + v.x + v.y + v.z;
        }
        int total = ws[31];
        __syncthreads();
        if (t == 0) s_carry += total;
        __syncthreads();
    }
    if (t == 0) g_rowptr[NN] = s_carry;
}

__global__ void scatter_k(const int* __restrict__ src, const int* __restrict__ dst) {
    int e = blockIdx.x * blockDim.x + threadIdx.x;
    if (e < EE) {
        int d = dst[e];
        int pos = g_rowptr[d] + atomicAdd(&g_cur[d], 1);
        g_csr[pos] = src[e];
    }
}

// ---------------------------------------------------------------------------
// bf16 split helpers
// ---------------------------------------------------------------------------
__device__ __forceinline__ void bf16_split(float v, __nv_bfloat16& h, __nv_bfloat16& l) {
    h = __float2bfloat16_rn(v);
    l = __float2bfloat16_rn(v - __bfloat162float(h));
}
__device__ __forceinline__ uint32_t pack_bf16(__nv_bfloat16 lo, __nv_bfloat16 hi) {
    __nv_bfloat162 p = __halves2bfloat162(lo, hi);
    return *reinterpret_cast<uint32_t*>(&p);
}

// Split ALL layer weights into fragment-linear layout, one launch.
// Fragment row r = ks*4 + q (q = quad lane); element (r, n) packs:
//   x = bf16h(W[2*k2a], W[2*k2a+1])   k2a = ks*8 + q
//   y = bf16h(W[2*k2b], W[2*k2b+1])   k2b = ks*8 + 4 + q
//   z,w = bf16l of same
__global__ void split_all_k(const float* __restrict__ W1,
                            const float* __restrict__ Whp)
{
    int tid = blockIdx.x * blockDim.x + threadIdx.x;
    const float* W;
    int r, n, off;
    if (tid < 8192) {                       // layer 0, K=128, 32 rows
        W = W1; r = tid >> 8; n = tid & 255; off = 0;
    } else {
        int t2 = tid - 8192;
        if (t2 >= 3 * 4096) return;
        int layer = t2 >> 12;               // 0..2
        W = Whp + (size_t)layer * DD * HD;
        r = (t2 & 4095) >> 8; n = t2 & 255;
        off = 8192 + layer * 4096;
    }
    int ks = r >> 2, q = r & 3;
    int k2a = ks * 8 + q;
    int k2b = ks * 8 + 4 + q;
    float wa0 = W[(2 * k2a) * 256 + n],     wa1 = W[(2 * k2a + 1) * 256 + n];
    float wb0 = W[(2 * k2b) * 256 + n],     wb1 = W[(2 * k2b + 1) * 256 + n];
    __nv_bfloat16 ha0, la0, ha1, la1, hb0, lb0, hb1, lb1;
    bf16_split(wa0, ha0, la0);
    bf16_split(wa1, ha1, la1);
    bf16_split(wb0, hb0, lb0);
    bf16_split(wb1, hb1, lb1);
    uint4 o;
    o.x = pack_bf16(ha0, ha1);
    o.y = pack_bf16(hb0, hb1);
    o.z = pack_bf16(la0, la1);
    o.w = pack_bf16(lb0, lb1);
    g_Wf[off + r * 256 + n] = o;
}

// ---------------------------------------------------------------------------
// bf16 3-term tensor-core GEMM + fused attention coefficients.
// feat[64 x 256] = A[64 x K] @ W[K x 256],  A=Ah+Al, W=Wh+Wl (bf16 splits),
// D = Ah*Wh + Ah*Wl + Al*Wh  (Al*Wl ~ 4e-6, dropped).
// B fragments loaded DIRECTLY from fragment-linear global W (L1-resident),
// one LDG.128 per (j, kstep). Only A staged in smem.
// Block: 256 thr = 8 warps, 2(M) x 4(N); warp tile m32 x n64 (1 head/warp).
// ---------------------------------------------------------------------------
__device__ __forceinline__ void mma_bf16(float* c, const uint32_t* a,
                                         uint32_t b0, uint32_t b1)
{
    asm volatile(
        "mma.sync.aligned.m16n8k16.row.col.f32.bf16.bf16.f32 "
        "{%0,%1,%2,%3}, {%4,%5,%6,%7}, {%8,%9}, {%0,%1,%2,%3};"
        : "+f"(c[0]), "+f"(c[1]), "+f"(c[2]), "+f"(c[3])
        : "r"(a[0]), "r"(a[1]), "r"(a[2]), "r"(a[3]), "r"(b0), "r"(b1));
}

template <int K>
__global__ void __launch_bounds__(256) gemm_mma_k(
    const float* __restrict__ hin, int wf_off,
    const float* __restrict__ al, const float* __restrict__ ar)
{
    constexpr int K2  = K / 2;
    constexpr int ASp = K2 + 4;   // ≡ 4 (mod 32): A frag loads conflict-free
    __shared__ uint32_t sAh[64 * ASp];
    __shared__ uint32_t sAl[64 * ASp];

    int t = threadIdx.x, lane = t & 31, wid = t >> 5;
    int wm = wid >> 2, wn = wid & 3;     // warp M-row, warp N-col (= head)
    int g = lane >> 2, q = lane & 3;     // groupID (row), quad lane
    int n0 = blockIdx.x * 64;

    // Stage A as packed bf16 hi/lo k-pairs; zero-fill rows >= NN
    for (int idx = t; idx < 64 * K2; idx += 256) {
        int r = idx / K2, k2 = idx % K2;
        float v0 = 0.f, v1 = 0.f;
        if (n0 + r < NN) {
            float2 vv = *(const float2*)&hin[(size_t)(n0 + r) * K + 2 * k2];
            v0 = vv.x; v1 = vv.y;
        }
        __nv_bfloat16 h0, l0, h1, l1;
        bf16_split(v0, h0, l0);
        bf16_split(v1, h1, l1);
        sAh[r * ASp + k2] = pack_bf16(h0, h1);
        sAl[r * ASp + k2] = pack_bf16(l0, l1);
    }
    __syncthreads();

    float c_[2][8][4];
    #pragma unroll
    for (int i = 0; i < 2; i++)
        #pragma unroll
        for (int j = 0; j < 8; j++)
            #pragma unroll
            for (int r = 0; r < 4; r++) c_[i][j][r] = 0.f;

    const uint4* wf = g_Wf + wf_off;

    #pragma unroll
    for (int ks = 0; ks < K / 16; ks++) {
        int k2b = ks * 8;
        uint32_t ah[2][4], alr[2][4];
        #pragma unroll
        for (int i = 0; i < 2; i++) {
            int r = wm * 32 + i * 16 + g;
            ah[i][0]  = sAh[r * ASp + k2b + q];
            ah[i][1]  = sAh[(r + 8) * ASp + k2b + q];
            ah[i][2]  = sAh[r * ASp + k2b + 4 + q];
            ah[i][3]  = sAh[(r + 8) * ASp + k2b + 4 + q];
            alr[i][0] = sAl[r * ASp + k2b + q];
            alr[i][1] = sAl[(r + 8) * ASp + k2b + q];
            alr[i][2] = sAl[r * ASp + k2b + 4 + q];
            alr[i][3] = sAl[(r + 8) * ASp + k2b + 4 + q];
        }
        #pragma unroll
        for (int j = 0; j < 8; j++) {
            int ncol = wn * 64 + j * 8 + g;
            uint4 f = __ldg(&wf[(ks * 4 + q) * 256 + ncol]);
            #pragma unroll
            for (int i = 0; i < 2; i++) {
                mma_bf16(c_[i][j], ah[i],  f.x, f.y);
                mma_bf16(c_[i][j], ah[i],  f.z, f.w);
                mma_bf16(c_[i][j], alr[i], f.x, f.y);
            }
        }
    }

    // Epilogue: store feat (fp16), fused el/er (this warp's head = wn, fp32)
    float alv[8][2], arv[8][2];
    #pragma unroll
    for (int j = 0; j < 8; j++) {
        int col = wn * 64 + j * 8 + 2 * q;
        alv[j][0] = al[col]; alv[j][1] = al[col + 1];
        arv[j][0] = ar[col]; arv[j][1] = ar[col + 1];
    }
    #pragma unroll
    for (int i = 0; i < 2; i++) {
        int rtop = n0 + wm * 32 + i * 16 + g;
        int rbot = rtop + 8;
        float plt = 0.f, prt = 0.f, plb = 0.f, prb = 0.f;
        #pragma unroll
        for (int j = 0; j < 8; j++) {
            int cb = wn * 64 + j * 8 + 2 * q;
            if (rtop < NN)
                *(__half2*)&g_feat_h[(size_t)rtop * HD + cb] =
                    __floats2half2_rn(c_[i][j][0], c_[i][j][1]);
            if (rbot < NN)
                *(__half2*)&g_feat_h[(size_t)rbot * HD + cb] =
                    __floats2half2_rn(c_[i][j][2], c_[i][j][3]);
            plt += c_[i][j][0] * alv[j][0] + c_[i][j][1] * alv[j][1];
            prt += c_[i][j][0] * arv[j][0] + c_[i][j][1] * arv[j][1];
            plb += c_[i][j][2] * alv[j][0] + c_[i][j][3] * alv[j][1];
            prb += c_[i][j][2] * arv[j][0] + c_[i][j][3] * arv[j][1];
        }
        #pragma unroll
        for (int o = 1; o <= 2; o <<= 1) {
            plt += __shfl_xor_sync(0xffffffffu, plt, o);
            prt += __shfl_xor_sync(0xffffffffu, prt, o);
            plb += __shfl_xor_sync(0xffffffffu, plb, o);
            prb += __shfl_xor_sync(0xffffffffu, prb, o);
        }
        if (q == 0) {
            if (rtop < NN) { g_el[rtop * HH + wn] = plt; g_er[rtop * HH + wn] = prt; }
            if (rbot < NN) { g_el[rbot * HH + wn] = plb; g_er[rbot * HH + wn] = prb; }
        }
    }
}

// ---------------------------------------------------------------------------
// Warp-per-node edge softmax + aggregation. 256 thr = 8 warps = 8 nodes/block.
// Lane c owns 16B (8 halves) of the 512B fp16 feature row -> gather is one
// LDG.128/lane/edge. All 4 heads inside the warp; no block barriers.
// Fast path deg<=32 (lane j owns edge j); serial fallback for larger.
// ---------------------------------------------------------------------------
__device__ __forceinline__ float lrelu(float e) {
    return e > 0.f ? e : NEG_SLOPE * e;
}

template <bool MEAN>
__global__ void __launch_bounds__(256) edge_agg_w(
    const float* __restrict__ b, float* __restrict__ out)
{
    __shared__ float s_w_all[8][HH][33];
    __shared__ int   s_src_all[8][32];

    int t = threadIdx.x, lane = t & 31, wid = t >> 5;
    int n = blockIdx.x * 8 + wid;
    if (n >= NN) return;

    float (*s_w)[33] = s_w_all[wid];
    int* s_src = s_src_all[wid];

    int rb  = g_rowptr[n];
    int deg = g_rowptr[n + 1] - rb;

    int h = lane >> 3;           // head owning this lane's 8 features
    float acc[8];
    #pragma unroll
    for (int i = 0; i < 8; i++) acc[i] = 0.f;

    const uint4* fb = (const uint4*)g_feat_h;   // 32 uint4 per node row

    if (deg > 0 && deg <= 32) {
        float4 er4 = *(const float4*)(g_er + n * HH);
        float e0 = -1e30f, e1 = -1e30f, e2 = -1e30f, e3 = -1e30f;
        if (lane < deg) {
            int sn = g_csr[rb + lane];
            s_src[lane] = sn;
            float4 el4 = *(const float4*)(g_el + sn * HH);
            e0 = lrelu(el4.x + er4.x);
            e1 = lrelu(el4.y + er4.y);
            e2 = lrelu(el4.z + er4.z);
            e3 = lrelu(el4.w + er4.w);
        }
        float m0 = e0, m1 = e1, m2 = e2, m3 = e3;
        #pragma unroll
        for (int o = 16; o; o >>= 1) {
            m0 = fmaxf(m0, __shfl_xor_sync(0xffffffffu, m0, o));
            m1 = fmaxf(m1, __shfl_xor_sync(0xffffffffu, m1, o));
            m2 = fmaxf(m2, __shfl_xor_sync(0xffffffffu, m2, o));
            m3 = fmaxf(m3, __shfl_xor_sync(0xffffffffu, m3, o));
        }
        float w0 = 0.f, w1 = 0.f, w2 = 0.f, w3 = 0.f;
        if (lane < deg) {
            w0 = __expf(e0 - m0);
            w1 = __expf(e1 - m1);
            w2 = __expf(e2 - m2);
            w3 = __expf(e3 - m3);
        }
        float s0 = w0, s1 = w1, s2 = w2, s3 = w3;
        #pragma unroll
        for (int o = 16; o; o >>= 1) {
            s0 += __shfl_xor_sync(0xffffffffu, s0, o);
            s1 += __shfl_xor_sync(0xffffffffu, s1, o);
            s2 += __shfl_xor_sync(0xffffffffu, s2, o);
            s3 += __shfl_xor_sync(0xffffffffu, s3, o);
        }
        if (lane < deg) {
            s_w[0][lane] = w0 / s0;
            s_w[1][lane] = w1 / s1;
            s_w[2][lane] = w2 / s2;
            s_w[3][lane] = w3 / s3;
        }
        __syncwarp();

        for (int j = 0; j < deg; j++) {
            int   sn = s_src[j];
            float w  = s_w[h][j];
            uint4 f  = fb[(size_t)sn * 32 + lane];
            float2 p0 = __half22float2(*(const __half2*)&f.x);
            float2 p1 = __half22float2(*(const __half2*)&f.y);
            float2 p2 = __half22float2(*(const __half2*)&f.z);
            float2 p3 = __half22float2(*(const __half2*)&f.w);
            acc[0] += w * p0.x; acc[1] += w * p0.y;
            acc[2] += w * p1.x; acc[3] += w * p1.y;
            acc[4] += w * p2.x; acc[5] += w * p2.y;
            acc[6] += w * p3.x; acc[7] += w * p3.y;
        }
    } else if (deg > 32) {
        // rare fallback: serial per-lane softmax on own head
        float er_h = g_er[n * HH + h];
        float m = -1e30f;
        for (int j = 0; j < deg; j++) {
            int sn = g_csr[rb + j];
            m = fmaxf(m, lrelu(g_el[sn * HH + h] + er_h));
        }
        float s = 0.f;
        for (int j = 0; j < deg; j++) {
            int sn = g_csr[rb + j];
            s += __expf(lrelu(g_el[sn * HH + h] + er_h) - m);
        }
        float inv = 1.0f / s;
        for (int j = 0; j < deg; j++) {
            int sn = g_csr[rb + j];
            float w = __expf(lrelu(g_el[sn * HH + h] + er_h) - m) * inv;
            uint4 f = fb[(size_t)sn * 32 + lane];
            float2 p0 = __half22float2(*(const __half2*)&f.x);
            float2 p1 = __half22float2(*(const __half2*)&f.y);
            float2 p2 = __half22float2(*(const __half2*)&f.z);
            float2 p3 = __half22float2(*(const __half2*)&f.w);
            acc[0] += w * p0.x; acc[1] += w * p0.y;
            acc[2] += w * p1.x; acc[3] += w * p1.y;
            acc[4] += w * p2.x; acc[5] += w * p2.y;
            acc[6] += w * p3.x; acc[7] += w * p3.y;
        }
    }

    if (MEAN) {
        #pragma unroll
        for (int o = 8; o <= 16; o <<= 1)
            #pragma unroll
            for (int i = 0; i < 8; i++)
                acc[i] += __shfl_down_sync(0xffffffffu, acc[i], o);
        if (lane < 8) {
            int d0 = lane * 8;
            float r[8];
            #pragma unroll
            for (int i = 0; i < 8; i++) {
                int d = d0 + i;
                r[i] = 0.25f * (acc[i] + b[d] + b[DD + d] + b[2 * DD + d] + b[3 * DD + d]);
            }
            float4* o4 = (float4*)(out + (size_t)n * DD + d0);
            o4[0] = make_float4(r[0], r[1], r[2], r[3]);
            o4[1] = make_float4(r[4], r[5], r[6], r[7]);
        }
    } else {
        int d0 = lane * 8;
        float r[8];
        #pragma unroll
        for (int i = 0; i < 8; i++) r[i] = acc[i] + b[d0 + i];
        float4* o4 = (float4*)(out + (size_t)n * HD + d0);
        o4[0] = make_float4(r[0], r[1], r[2], r[3]);
        o4[1] = make_float4(r[4], r[5], r[6], r[7]);
    }
}

// ---------------------------------------------------------------------------
// Final Linear(256->64) + LayerNorm (no affine). 16 nodes/block, 64 threads.
// ---------------------------------------------------------------------------
__global__ void __launch_bounds__(64) final_ln_k(
    const float* __restrict__ hin, const float* __restrict__ Wo,
    const float* __restrict__ bo, float* __restrict__ out)
{
    constexpr int NB = 16;
    constexpr int K4 = HD / 4;               // 64
    __shared__ float4 sh4[NB * K4];          // 16 KB
    __shared__ float so[NB * DD];            // 4 KB
    __shared__ float mu_s[NB], rs_s[NB];
    int t = threadIdx.x;
    int n0 = blockIdx.x * NB;

    const float4* hin4 = (const float4*)(hin + (size_t)n0 * HD);
    for (int idx = t; idx < NB * K4; idx += 64)
        sh4[idx] = hin4[idx];
    __syncthreads();

    float acc[NB];
    #pragma unroll
    for (int i = 0; i < NB; i++) acc[i] = 0.f;
    float bv = bo[t];

    for (int k4 = 0; k4 < K4; k4++) {
        int k = k4 * 4;
        float w0 = __ldg(&Wo[(k + 0) * DD + t]);
        float w1 = __ldg(&Wo[(k + 1) * DD + t]);
        float w2 = __ldg(&Wo[(k + 2) * DD + t]);
        float w3 = __ldg(&Wo[(k + 3) * DD + t]);
        #pragma unroll
        for (int i = 0; i < NB; i++) {
            float4 s = sh4[i * K4 + k4];
            acc[i] += s.x * w0;
            acc[i] += s.y * w1;
            acc[i] += s.z * w2;
            acc[i] += s.w * w3;
        }
    }

    #pragma unroll
    for (int i = 0; i < NB; i++) so[i * DD + t] = acc[i] + bv;
    __syncthreads();

    if (t < NB) {
        float s = 0.f;
        for (int j = 0; j < DD; j++) s += so[t * DD + j];
        float mu = s * (1.0f / DD);
        float s2 = 0.f;
        for (int j = 0; j < DD; j++) {
            float d = so[t * DD + j] - mu;
            s2 += d * d;
        }
        mu_s[t] = mu;
        rs_s[t] = rsqrtf(s2 * (1.0f / DD) + 1e-5f);
    }
    __syncthreads();

    #pragma unroll
    for (int i = 0; i < NB; i++)
        out[(size_t)(n0 + i) * DD + t] = (so[i * DD + t] - mu_s[i]) * rs_s[i];
}

// ---------------------------------------------------------------------------
// Launch: inputs (metadata order):
// 0 in_feat[N,128] 1 src[E] 2 dst[E] 3 W1[128,256] 4 al1[4,64] 5 ar1[4,64]
// 6 b1[256] 7 Wh[3,64,256] 8 alh[3,4,64] 9 arh[3,4,64] 10 bh[3,256]
// 11 Wo[256,64] 12 bo[64]  -> out float32 [N,64]
// ---------------------------------------------------------------------------
extern "C" void kernel_launch(void* const* d_in, const int* in_sizes, int n_in,
                              void* d_out, int out_size)
{
    const float* in_feat = (const float*)d_in[0];
    const int*   src     = (const int*)d_in[1];
    const int*   dst     = (const int*)d_in[2];
    const float* W1      = (const float*)d_in[3];
    const float* al1     = (const float*)d_in[4];
    const float* ar1     = (const float*)d_in[5];
    const float* b1      = (const float*)d_in[6];
    const float* Whp     = (const float*)d_in[7];
    const float* alh     = (const float*)d_in[8];
    const float* arh     = (const float*)d_in[9];
    const float* bh      = (const float*)d_in[10];
    const float* Wo      = (const float*)d_in[11];
    const float* bo      = (const float*)d_in[12];
    float* out = (float*)d_out;

    float* g_h_ptr;
    cudaGetSymbolAddress((void**)&g_h_ptr, g_h);

    // All W splits in one launch (20480 threads)
    split_all_k<<<80, 256>>>(W1, Whp);

    // CSR build
    zero_cur_k<<<(NN + 255) / 256, 256>>>();
    hist_k<<<(EE + 255) / 256, 256>>>(dst);
    scan_k<<<1, 1024>>>();
    scatter_k<<<(EE + 255) / 256, 256>>>(src, dst);

    const int GMMA = (NN + 63) / 64;   // 782 blocks
    const int GAGG = (NN + 7) / 8;     // 6250 blocks (8 nodes/block)

    // layer wf offsets (uint4 units)
    const int WF0 = 0, WF1 = 8192, WF2 = 8192 + 4096, WF3 = 8192 + 2 * 4096;

    // Layer 1: conv1 (K=128), mean over heads -> g_h[N,64]
    gemm_mma_k<IN_F><<<GMMA, 256>>>(in_feat, WF0, al1, ar1);
    edge_agg_w<true><<<GAGG, 256>>>(b1, g_h_ptr);

    // Hidden layers 0,1 (mean)
    gemm_mma_k<DD><<<GMMA, 256>>>(g_h_ptr, WF1, alh + 0 * HD, arh + 0 * HD);
    edge_agg_w<true><<<GAGG, 256>>>(bh + 0 * HD, g_h_ptr);
    gemm_mma_k<DD><<<GMMA, 256>>>(g_h_ptr, WF2, alh + 1 * HD, arh + 1 * HD);
    edge_agg_w<true><<<GAGG, 256>>>(bh + 1 * HD, g_h_ptr);

    // Hidden layer 2 (full [N,H,D] output)
    gemm_mma_k<DD><<<GMMA, 256>>>(g_h_ptr, WF3, alh + 2 * HD, arh + 2 * HD);
    edge_agg_w<false><<<GAGG, 256>>>(bh + 2 * HD, g_h_ptr);

    // Final linear + LayerNorm -> d_out
    final_ln_k<<<NN / 16, 64>>>(g_h_ptr, Wo, bo, out);
}

// round 10
// speedup vs baseline: 1.0788x; 1.0788x over previous
#include <cuda_runtime.h>
#include <cuda_bf16.h>
#include <cuda_fp16.h>
#include <cstdint>

// Problem constants (match reference_code)
#define NN 50000      // nodes
#define EE 800000     // edges
#define IN_F 128
#define DD 64
#define HH 4
#define HD 256        // H*D
#define NEG_SLOPE 0.2f

#define SCAN_CHUNK 4096
#define SCAN_BLOCKS ((NN + SCAN_CHUNK - 1) / SCAN_CHUNK)   // 13

// ---------------------------------------------------------------------------
// Scratch (static __device__ arrays — no allocation allowed)
// ---------------------------------------------------------------------------
__device__ __half   g_feat_h[(size_t)NN * HD]; // projected features [N,256] fp16
__device__ float    g_h[(size_t)NN * HD];      // layer io buffer (fp32)
__device__ float    g_el[(size_t)NN * HH];
__device__ float    g_er[(size_t)NN * HH];
__device__ int      g_rowptr[NN + 1];
__device__ int      g_cur[NN];
__device__ int      g_csr[EE];                 // src per CSR slot (sorted by dst)
__device__ int      g_bsum[SCAN_BLOCKS];       // scan phase-1 block totals
// W bf16 hi/lo, k-pairs packed, ALL layers: L0 64*256, L1-3 each 32*256
__device__ uint32_t g_Wph[16384 + 3 * 8192];
__device__ uint32_t g_Wpl[16384 + 3 * 8192];

// ---------------------------------------------------------------------------
// CSR build: zero -> histogram(dst) -> scan1 -> scan2 -> scatter
// ---------------------------------------------------------------------------
__global__ void zero_cur_k() {
    int i = blockIdx.x * blockDim.x + threadIdx.x;
    if (i < NN) g_cur[i] = 0;
}

__global__ void hist_k(const int* __restrict__ dst) {
    int e = blockIdx.x * blockDim.x + threadIdx.x;
    if (e < EE) atomicAdd(&g_cur[dst[e]], 1);
}

// Phase 1: each block locally exclusive-scans its 4096-chunk of g_cur into
// g_rowptr (local values), re-zeros g_cur, writes chunk total to g_bsum.
__global__ void __launch_bounds__(1024) scan1_k() {
    __shared__ int ws[32];
    int t = threadIdx.x, lane = t & 31, wid = t >> 5;
    int i0 = blockIdx.x * SCAN_CHUNK + t * 4;
    int4 v = make_int4(0, 0, 0, 0);
    if (i0 < NN) {
        v = *(const int4*)&g_cur[i0];
        *(int4*)&g_cur[i0] = make_int4(0, 0, 0, 0);
    }
    int tsum = v.x + v.y + v.z + v.w;
    int x = tsum;
    #pragma unroll
    for (int o = 1; o < 32; o <<= 1) {
        int y = __shfl_up_sync(0xffffffffu, x, o);
        if (lane >= o) x += y;
    }
    if (lane == 31) ws[wid] = x;
    __syncthreads();
    if (wid == 0) {
        int y = ws[lane];
        #pragma unroll
        for (int o = 1; o < 32; o <<= 1) {
            int z = __shfl_up_sync(0xffffffffu, y, o);
            if (lane >= o) y += z;
        }
        ws[lane] = y;
    }
    __syncthreads();
    int excl = x - tsum + (wid ? ws[wid - 1] : 0);
    if (i0 < NN) {
        g_rowptr[i0]     = excl;
        g_rowptr[i0 + 1] = excl + v.x;
        g_rowptr[i0 + 2] = excl + v.x + v.y;
        g_rowptr[i0 + 3] = excl + v.x + v.y + v.z;
    }
    if (t == 0) g_bsum[blockIdx.x] = 0;    // will be overwritten below
    __syncthreads();
    if (t == 1023) g_bsum[blockIdx.x] = ws[31];
}

// Phase 2: each block adds the prefix of earlier block totals to its chunk.
__global__ void __launch_bounds__(1024) scan2_k() {
    __shared__ int s_off, s_tot;
    int t = threadIdx.x, b = blockIdx.x;
    if (t == 0) {
        int off = 0, tot = 0;
        #pragma unroll
        for (int j = 0; j < SCAN_BLOCKS; j++) {
            int v = g_bsum[j];
            if (j < b) off += v;
            tot += v;
        }
        s_off = off; s_tot = tot;
    }
    __syncthreads();
    int off = s_off;
    int i0 = b * SCAN_CHUNK + t * 4;
    if (off != 0 && i0 < NN) {
        int4 r = *(int4*)&g_rowptr[i0];
        r.x += off; r.y += off; r.z += off; r.w += off;
        *(int4*)&g_rowptr[i0] = r;
    }
    if (b == 0 && t == 0) g_rowptr[NN] = s_tot;
}

__global__ void scatter_k(const int* __restrict__ src, const int* __restrict__ dst) {
    int e = blockIdx.x * blockDim.x + threadIdx.x;
    if (e < EE) {
        int d = dst[e];
        int pos = g_rowptr[d] + atomicAdd(&g_cur[d], 1);
        g_csr[pos] = src[e];
    }
}

// ---------------------------------------------------------------------------
// bf16 split helpers
// ---------------------------------------------------------------------------
__device__ __forceinline__ void bf16_split(float v, __nv_bfloat16& h, __nv_bfloat16& l) {
    h = __float2bfloat16_rn(v);
    l = __float2bfloat16_rn(v - __bfloat162float(h));
}
__device__ __forceinline__ uint32_t pack_bf16(__nv_bfloat16 lo, __nv_bfloat16 hi) {
    __nv_bfloat162 p = __halves2bfloat162(lo, hi);
    return *reinterpret_cast<uint32_t*>(&p);
}

// Split ALL layer weights (k-pair packed hi/lo), one launch.
// Element layout per layer: idx = k2*256 + n.
__global__ void split_all_k(const float* __restrict__ W1,
                            const float* __restrict__ Whp)
{
    int tid = blockIdx.x * blockDim.x + threadIdx.x;
    const float* W;
    int local, off;
    if (tid < 16384) {                      // layer 0, K2=64
        W = W1; local = tid; off = 0;
    } else {
        int t2 = tid - 16384;
        if (t2 >= 3 * 8192) return;
        int layer = t2 >> 13;               // 0..2
        W = Whp + (size_t)layer * DD * HD;
        local = t2 & 8191;
        off = 16384 + layer * 8192;
    }
    int k2 = local >> 8, n = local & 255;
    float w0 = W[(2 * k2) * 256 + n];
    float w1 = W[(2 * k2 + 1) * 256 + n];
    __nv_bfloat16 h0, l0, h1, l1;
    bf16_split(w0, h0, l0);
    bf16_split(w1, h1, l1);
    g_Wph[off + local] = pack_bf16(h0, h1);
    g_Wpl[off + local] = pack_bf16(l0, l1);
}

// ---------------------------------------------------------------------------
// bf16 3-term tensor-core GEMM + fused attention coefficients (R8 form:
// smem-staged W — best measured). D = Ah*Wh + Ah*Wl + Al*Wh.
// Block: 256 thr = 8 warps, 2(M) x 4(N); warp tile m32 x n64 (1 head/warp).
// ---------------------------------------------------------------------------
__device__ __forceinline__ void mma_bf16(float* c, const uint32_t* a,
                                         uint32_t b0, uint32_t b1)
{
    asm volatile(
        "mma.sync.aligned.m16n8k16.row.col.f32.bf16.bf16.f32 "
        "{%0,%1,%2,%3}, {%4,%5,%6,%7}, {%8,%9}, {%0,%1,%2,%3};"
        : "+f"(c[0]), "+f"(c[1]), "+f"(c[2]), "+f"(c[3])
        : "r"(a[0]), "r"(a[1]), "r"(a[2]), "r"(a[3]), "r"(b0), "r"(b1));
}

template <int K>
__global__ void __launch_bounds__(256) gemm_mma_k(
    const float* __restrict__ hin, int w_off,
    const float* __restrict__ al, const float* __restrict__ ar)
{
    constexpr int K2  = K / 2;
    constexpr int ASp = K2 + 4;   // ≡ 4 (mod 32): A frag loads conflict-free
    constexpr int WSp = 264;      // ≡ 8 (mod 32): B frag loads conflict-free
    extern __shared__ uint32_t smu[];
    uint32_t* sAh = smu;                         // 64*ASp
    uint32_t* sAl = sAh + 64 * ASp;              // 64*ASp
    uint32_t* sWh = sAl + 64 * ASp;              // K2*WSp
    uint32_t* sWl = sWh + K2 * WSp;              // K2*WSp

    int t = threadIdx.x, lane = t & 31, wid = t >> 5;
    int wm = wid >> 2, wn = wid & 3;     // warp M-row, warp N-col (= head)
    int g = lane >> 2, q = lane & 3;     // groupID (row), quad lane
    int n0 = blockIdx.x * 64;

    // Stage A as packed bf16 hi/lo k-pairs; zero-fill rows >= NN
    for (int idx = t; idx < 64 * K2; idx += 256) {
        int r = idx / K2, k2 = idx % K2;
        float v0 = 0.f, v1 = 0.f;
        if (n0 + r < NN) {
            float2 vv = *(const float2*)&hin[(size_t)(n0 + r) * K + 2 * k2];
            v0 = vv.x; v1 = vv.y;
        }
        __nv_bfloat16 h0, l0, h1, l1;
        bf16_split(v0, h0, l0);
        bf16_split(v1, h1, l1);
        sAh[r * ASp + k2] = pack_bf16(h0, h1);
        sAl[r * ASp + k2] = pack_bf16(l0, l1);
    }
    // Stage full W (hi/lo)
    for (int idx = t; idx < K2 * 256; idx += 256) {
        int k2 = idx >> 8, n = idx & 255;
        sWh[k2 * WSp + n] = g_Wph[w_off + idx];
        sWl[k2 * WSp + n] = g_Wpl[w_off + idx];
    }
    __syncthreads();

    float c_[2][8][4];
    #pragma unroll
    for (int i = 0; i < 2; i++)
        #pragma unroll
        for (int j = 0; j < 8; j++)
            #pragma unroll
            for (int r = 0; r < 4; r++) c_[i][j][r] = 0.f;

    for (int ks = 0; ks < K / 16; ks++) {
        int k2b = ks * 8;
        uint32_t ah[2][4], alr[2][4];
        #pragma unroll
        for (int i = 0; i < 2; i++) {
            int r = wm * 32 + i * 16 + g;
            ah[i][0]  = sAh[r * ASp + k2b + q];
            ah[i][1]  = sAh[(r + 8) * ASp + k2b + q];
            ah[i][2]  = sAh[r * ASp + k2b + 4 + q];
            ah[i][3]  = sAh[(r + 8) * ASp + k2b + 4 + q];
            alr[i][0] = sAl[r * ASp + k2b + q];
            alr[i][1] = sAl[(r + 8) * ASp + k2b + q];
            alr[i][2] = sAl[r * ASp + k2b + 4 + q];
            alr[i][3] = sAl[(r + 8) * ASp + k2b + 4 + q];
        }
        #pragma unroll
        for (int j = 0; j < 8; j++) {
            int ncol = wn * 64 + j * 8 + g;
            uint32_t bh0 = sWh[(k2b + q) * WSp + ncol];
            uint32_t bh1 = sWh[(k2b + 4 + q) * WSp + ncol];
            uint32_t bl0 = sWl[(k2b + q) * WSp + ncol];
            uint32_t bl1 = sWl[(k2b + 4 + q) * WSp + ncol];
            #pragma unroll
            for (int i = 0; i < 2; i++) {
                mma_bf16(c_[i][j], ah[i], bh0, bh1);
                mma_bf16(c_[i][j], ah[i], bl0, bl1);
                mma_bf16(c_[i][j], alr[i], bh0, bh1);
            }
        }
    }

    // Epilogue: store feat (fp16), fused el/er (this warp's head = wn, fp32)
    float alv[8][2], arv[8][2];
    #pragma unroll
    for (int j = 0; j < 8; j++) {
        int col = wn * 64 + j * 8 + 2 * q;
        alv[j][0] = al[col]; alv[j][1] = al[col + 1];
        arv[j][0] = ar[col]; arv[j][1] = ar[col + 1];
    }
    #pragma unroll
    for (int i = 0; i < 2; i++) {
        int rtop = n0 + wm * 32 + i * 16 + g;
        int rbot = rtop + 8;
        float plt = 0.f, prt = 0.f, plb = 0.f, prb = 0.f;
        #pragma unroll
        for (int j = 0; j < 8; j++) {
            int cb = wn * 64 + j * 8 + 2 * q;
            if (rtop < NN)
                *(__half2*)&g_feat_h[(size_t)rtop * HD + cb] =
                    __floats2half2_rn(c_[i][j][0], c_[i][j][1]);
            if (rbot < NN)
                *(__half2*)&g_feat_h[(size_t)rbot * HD + cb] =
                    __floats2half2_rn(c_[i][j][2], c_[i][j][3]);
            plt += c_[i][j][0] * alv[j][0] + c_[i][j][1] * alv[j][1];
            prt += c_[i][j][0] * arv[j][0] + c_[i][j][1] * arv[j][1];
            plb += c_[i][j][2] * alv[j][0] + c_[i][j][3] * alv[j][1];
            prb += c_[i][j][2] * arv[j][0] + c_[i][j][3] * arv[j][1];
        }
        #pragma unroll
        for (int o = 1; o <= 2; o <<= 1) {
            plt += __shfl_xor_sync(0xffffffffu, plt, o);
            prt += __shfl_xor_sync(0xffffffffu, prt, o);
            plb += __shfl_xor_sync(0xffffffffu, plb, o);
            prb += __shfl_xor_sync(0xffffffffu, prb, o);
        }
        if (q == 0) {
            if (rtop < NN) { g_el[rtop * HH + wn] = plt; g_er[rtop * HH + wn] = prt; }
            if (rbot < NN) { g_el[rbot * HH + wn] = plb; g_er[rbot * HH + wn] = prb; }
        }
    }
}

// ---------------------------------------------------------------------------
// Warp-per-node edge softmax + aggregation (R8 form — best measured).
// ---------------------------------------------------------------------------
__device__ __forceinline__ float lrelu(float e) {
    return e > 0.f ? e : NEG_SLOPE * e;
}

template <bool MEAN>
__global__ void __launch_bounds__(256) edge_agg_w(
    const float* __restrict__ b, float* __restrict__ out)
{
    __shared__ float s_w_all[8][HH][33];
    __shared__ int   s_src_all[8][32];

    int t = threadIdx.x, lane = t & 31, wid = t >> 5;
    int n = blockIdx.x * 8 + wid;
    if (n >= NN) return;

    float (*s_w)[33] = s_w_all[wid];
    int* s_src = s_src_all[wid];

    int rb  = g_rowptr[n];
    int deg = g_rowptr[n + 1] - rb;

    int h = lane >> 3;
    float acc[8];
    #pragma unroll
    for (int i = 0; i < 8; i++) acc[i] = 0.f;

    const uint4* fb = (const uint4*)g_feat_h;

    if (deg > 0 && deg <= 32) {
        float4 er4 = *(const float4*)(g_er + n * HH);
        float e0 = -1e30f, e1 = -1e30f, e2 = -1e30f, e3 = -1e30f;
        if (lane < deg) {
            int sn = g_csr[rb + lane];
            s_src[lane] = sn;
            float4 el4 = *(const float4*)(g_el + sn * HH);
            e0 = lrelu(el4.x + er4.x);
            e1 = lrelu(el4.y + er4.y);
            e2 = lrelu(el4.z + er4.z);
            e3 = lrelu(el4.w + er4.w);
        }
        float m0 = e0, m1 = e1, m2 = e2, m3 = e3;
        #pragma unroll
        for (int o = 16; o; o >>= 1) {
            m0 = fmaxf(m0, __shfl_xor_sync(0xffffffffu, m0, o));
            m1 = fmaxf(m1, __shfl_xor_sync(0xffffffffu, m1, o));
            m2 = fmaxf(m2, __shfl_xor_sync(0xffffffffu, m2, o));
            m3 = fmaxf(m3, __shfl_xor_sync(0xffffffffu, m3, o));
        }
        float w0 = 0.f, w1 = 0.f, w2 = 0.f, w3 = 0.f;
        if (lane < deg) {
            w0 = __expf(e0 - m0);
            w1 = __expf(e1 - m1);
            w2 = __expf(e2 - m2);
            w3 = __expf(e3 - m3);
        }
        float s0 = w0, s1 = w1, s2 = w2, s3 = w3;
        #pragma unroll
        for (int o = 16; o; o >>= 1) {
            s0 += __shfl_xor_sync(0xffffffffu, s0, o);
            s1 += __shfl_xor_sync(0xffffffffu, s1, o);
            s2 += __shfl_xor_sync(0xffffffffu, s2, o);
            s3 += __shfl_xor_sync(0xffffffffu, s3, o);
        }
        if (lane < deg) {
            s_w[0][lane] = w0 / s0;
            s_w[1][lane] = w1 / s1;
            s_w[2][lane] = w2 / s2;
            s_w[3][lane] = w3 / s3;
        }
        __syncwarp();

        for (int j = 0; j < deg; j++) {
            int   sn = s_src[j];
            float w  = s_w[h][j];
            uint4 f  = fb[(size_t)sn * 32 + lane];
            float2 p0 = __half22float2(*(const __half2*)&f.x);
            float2 p1 = __half22float2(*(const __half2*)&f.y);
            float2 p2 = __half22float2(*(const __half2*)&f.z);
            float2 p3 = __half22float2(*(const __half2*)&f.w);
            acc[0] += w * p0.x; acc[1] += w * p0.y;
            acc[2] += w * p1.x; acc[3] += w * p1.y;
            acc[4] += w * p2.x; acc[5] += w * p2.y;
            acc[6] += w * p3.x; acc[7] += w * p3.y;
        }
    } else if (deg > 32) {
        float er_h = g_er[n * HH + h];
        float m = -1e30f;
        for (int j = 0; j < deg; j++) {
            int sn = g_csr[rb + j];
            m = fmaxf(m, lrelu(g_el[sn * HH + h] + er_h));
        }
        float s = 0.f;
        for (int j = 0; j < deg; j++) {
            int sn = g_csr[rb + j];
            s += __expf(lrelu(g_el[sn * HH + h] + er_h) - m);
        }
        float inv = 1.0f / s;
        for (int j = 0; j < deg; j++) {
            int sn = g_csr[rb + j];
            float w = __expf(lrelu(g_el[sn * HH + h] + er_h) - m) * inv;
            uint4 f = fb[(size_t)sn * 32 + lane];
            float2 p0 = __half22float2(*(const __half2*)&f.x);
            float2 p1 = __half22float2(*(const __half2*)&f.y);
            float2 p2 = __half22float2(*(const __half2*)&f.z);
            float2 p3 = __half22float2(*(const __half2*)&f.w);
            acc[0] += w * p0.x; acc[1] += w * p0.y;
            acc[2] += w * p1.x; acc[3] += w * p1.y;
            acc[4] += w * p2.x; acc[5] += w * p2.y;
            acc[6] += w * p3.x; acc[7] += w * p3.y;
        }
    }

    if (MEAN) {
        #pragma unroll
        for (int o = 8; o <= 16; o <<= 1)
            #pragma unroll
            for (int i = 0; i < 8; i++)
                acc[i] += __shfl_down_sync(0xffffffffu, acc[i], o);
        if (lane < 8) {
            int d0 = lane * 8;
            float r[8];
            #pragma unroll
            for (int i = 0; i < 8; i++) {
                int d = d0 + i;
                r[i] = 0.25f * (acc[i] + b[d] + b[DD + d] + b[2 * DD + d] + b[3 * DD + d]);
            }
            float4* o4 = (float4*)(out + (size_t)n * DD + d0);
            o4[0] = make_float4(r[0], r[1], r[2], r[3]);
            o4[1] = make_float4(r[4], r[5], r[6], r[7]);
        }
    } else {
        int d0 = lane * 8;
        float r[8];
        #pragma unroll
        for (int i = 0; i < 8; i++) r[i] = acc[i] + b[d0 + i];
        float4* o4 = (float4*)(out + (size_t)n * HD + d0);
        o4[0] = make_float4(r[0], r[1], r[2], r[3]);
        o4[1] = make_float4(r[4], r[5], r[6], r[7]);
    }
}

// ---------------------------------------------------------------------------
// Final Linear(256->64) + LayerNorm (no affine). 16 nodes/block, 64 threads.
// ---------------------------------------------------------------------------
__global__ void __launch_bounds__(64) final_ln_k(
    const float* __restrict__ hin, const float* __restrict__ Wo,
    const float* __restrict__ bo, float* __restrict__ out)
{
    constexpr int NB = 16;
    constexpr int K4 = HD / 4;               // 64
    __shared__ float4 sh4[NB * K4];          // 16 KB
    __shared__ float so[NB * DD];            // 4 KB
    __shared__ float mu_s[NB], rs_s[NB];
    int t = threadIdx.x;
    int n0 = blockIdx.x * NB;

    const float4* hin4 = (const float4*)(hin + (size_t)n0 * HD);
    for (int idx = t; idx < NB * K4; idx += 64)
        sh4[idx] = hin4[idx];
    __syncthreads();

    float acc[NB];
    #pragma unroll
    for (int i = 0; i < NB; i++) acc[i] = 0.f;
    float bv = bo[t];

    for (int k4 = 0; k4 < K4; k4++) {
        int k = k4 * 4;
        float w0 = __ldg(&Wo[(k + 0) * DD + t]);
        float w1 = __ldg(&Wo[(k + 1) * DD + t]);
        float w2 = __ldg(&Wo[(k + 2) * DD + t]);
        float w3 = __ldg(&Wo[(k + 3) * DD + t]);
        #pragma unroll
        for (int i = 0; i < NB; i++) {
            float4 s = sh4[i * K4 + k4];
            acc[i] += s.x * w0;
            acc[i] += s.y * w1;
            acc[i] += s.z * w2;
            acc[i] += s.w * w3;
        }
    }

    #pragma unroll
    for (int i = 0; i < NB; i++) so[i * DD + t] = acc[i] + bv;
    __syncthreads();

    if (t < NB) {
        float s = 0.f;
        for (int j = 0; j < DD; j++) s += so[t * DD + j];
        float mu = s * (1.0f / DD);
        float s2 = 0.f;
        for (int j = 0; j < DD; j++) {
            float d = so[t * DD + j] - mu;
            s2 += d * d;
        }
        mu_s[t] = mu;
        rs_s[t] = rsqrtf(s2 * (1.0f / DD) + 1e-5f);
    }
    __syncthreads();

    #pragma unroll
    for (int i = 0; i < NB; i++)
        out[(size_t)(n0 + i) * DD + t] = (so[i * DD + t] - mu_s[i]) * rs_s[i];
}

// ---------------------------------------------------------------------------
// Launch: inputs (metadata order):
// 0 in_feat[N,128] 1 src[E] 2 dst[E] 3 W1[128,256] 4 al1[4,64] 5 ar1[4,64]
// 6 b1[256] 7 Wh[3,64,256] 8 alh[3,4,64] 9 arh[3,4,64] 10 bh[3,256]
// 11 Wo[256,64] 12 bo[64]  -> out float32 [N,64]
// ---------------------------------------------------------------------------
extern "C" void kernel_launch(void* const* d_in, const int* in_sizes, int n_in,
                              void* d_out, int out_size)
{
    const float* in_feat = (const float*)d_in[0];
    const int*   src     = (const int*)d_in[1];
    const int*   dst     = (const int*)d_in[2];
    const float* W1      = (const float*)d_in[3];
    const float* al1     = (const float*)d_in[4];
    const float* ar1     = (const float*)d_in[5];
    const float* b1      = (const float*)d_in[6];
    const float* Whp     = (const float*)d_in[7];
    const float* alh     = (const float*)d_in[8];
    const float* arh     = (const float*)d_in[9];
    const float* bh      = (const float*)d_in[10];
    const float* Wo      = (const float*)d_in[11];
    const float* bo      = (const float*)d_in[12];
    float* out = (float*)d_out;

    float* g_h_ptr;
    cudaGetSymbolAddress((void**)&g_h_ptr, g_h);

    // smem: 2*64*ASp + 2*K2*WSp uint32
    const int SMEM1 = (2 * 64 * (IN_F / 2 + 4) + 2 * (IN_F / 2) * 264) * 4; // 169984
    const int SMEMH = (2 * 64 * (DD / 2 + 4) + 2 * (DD / 2) * 264) * 4;     //  86016
    cudaFuncSetAttribute(gemm_mma_k<IN_F>,
                         cudaFuncAttributeMaxDynamicSharedMemorySize, SMEM1);
    cudaFuncSetAttribute(gemm_mma_k<DD>,
                         cudaFuncAttributeMaxDynamicSharedMemorySize, SMEMH);

    // All W splits in one launch (16384 + 24576 = 40960 threads)
    split_all_k<<<160, 256>>>(W1, Whp);

    // CSR build (parallel 2-phase scan)
    zero_cur_k<<<(NN + 255) / 256, 256>>>();
    hist_k<<<(EE + 255) / 256, 256>>>(dst);
    scan1_k<<<SCAN_BLOCKS, 1024>>>();
    scan2_k<<<SCAN_BLOCKS, 1024>>>();
    scatter_k<<<(EE + 255) / 256, 256>>>(src, dst);

    const int GMMA = (NN + 63) / 64;   // 782 blocks
    const int GAGG = (NN + 7) / 8;     // 6250 blocks (8 nodes/block)

    // layer W offsets (uint32 units, k-pair packed)
    const int WF0 = 0, WF1 = 16384, WF2 = 16384 + 8192, WF3 = 16384 + 2 * 8192;

    // Layer 1: conv1 (K=128), mean over heads -> g_h[N,64]
    gemm_mma_k<IN_F><<<GMMA, 256, SMEM1>>>(in_feat, WF0, al1, ar1);
    edge_agg_w<true><<<GAGG, 256>>>(b1, g_h_ptr);

    // Hidden layers 0,1 (mean)
    gemm_mma_k<DD><<<GMMA, 256, SMEMH>>>(g_h_ptr, WF1, alh + 0 * HD, arh + 0 * HD);
    edge_agg_w<true><<<GAGG, 256>>>(bh + 0 * HD, g_h_ptr);
    gemm_mma_k<DD><<<GMMA, 256, SMEMH>>>(g_h_ptr, WF2, alh + 1 * HD, arh + 1 * HD);
    edge_agg_w<true><<<GAGG, 256>>>(bh + 1 * HD, g_h_ptr);

    // Hidden layer 2 (full [N,H,D] output)
    gemm_mma_k<DD><<<GMMA, 256, SMEMH>>>(g_h_ptr, WF3, alh + 2 * HD, arh + 2 * HD);
    edge_agg_w<false><<<GAGG, 256>>>(bh + 2 * HD, g_h_ptr);

    // Final linear + LayerNorm -> d_out
    final_ln_k<<<NN / 16, 64>>>(g_h_ptr, Wo, bo, out);
}